// round 16
// baseline (speedup 1.0000x reference)
#include <cuda_runtime.h>
#include <cstdint>

#define NSAMP 256
#define EMB   120
#define DIN   64
#define MODES 16
#define NPH   8

#define PIf 3.14159265358979323846f

typedef unsigned long long ull;

#define VROW 18              // padded row stride (float2 units)
#define NPAIR 32640
#define NBLK  (NPAIR / 8)    // 4080 blocks

// Persistent scratch for V, stored TRANSPOSED: [n][c][m] (c=0..7, m=0..15)
__device__ float2 g_V[NSAMP * NPH * MODES];
// Producer/consumer flags + completion counter (reset by last block each launch)
__device__ volatile unsigned g_done[NSAMP];
__device__ unsigned g_fin;

__device__ __forceinline__ float2 cmul(float2 a, float2 b) {
    return make_float2(a.x * b.x - a.y * b.y, a.x * b.y + a.y * b.x);
}

// Packed dual-FMA on native 64-bit operands (FFMA2, one issue slot)
__device__ __forceinline__ ull ffma2p(ull a, ull b, ull c) {
    ull d;
    asm("fma.rn.f32x2 %0, %1, %2, %3;" : "=l"(d) : "l"(a), "l"(b), "l"(c));
    return d;
}
union pk { ull u; float2 f; };
__device__ __forceinline__ ull pack2(float x, float y) {
    pk v; v.f = make_float2(x, y); return v.u;
}
__device__ __forceinline__ float2 unpack2(ull a) {
    pk v; v.u = a; return v.f;
}

// ---------------------------------------------------------------------------
// Fused kernel: blocks 0..255 produce x_emb + V[sample bid], publish flags;
// all blocks then run one warp per pair (a<b), spinning on the two flags.
// ---------------------------------------------------------------------------
__global__ void __launch_bounds__(256, 4) fused_kernel(
    const float* __restrict__ x,
    const float* __restrict__ W,
    const float* __restrict__ b,
    float* __restrict__ out_emb,
    float* __restrict__ Kout)
{
    const int bid = blockIdx.x;
    const int tid = threadIdx.x;

    // ---- emb + V phase (producer blocks only) ----
    __shared__ float xs[DIN];
    __shared__ float semb[EMB];
    __shared__ float4 trig[60];

    if (bid < NSAMP) {
        const int n = bid;
        const int t = tid;

        if (t < DIN) xs[t] = x[n * DIN + t];
        if (t == 255) Kout[n * NSAMP + n] = 1.0f;   // diagonal of K
        __syncthreads();

        if (t < EMB) {
            float acc = b[t];
            const float* wr = W + t * DIN;
            #pragma unroll
            for (int j = 0; j < DIN; j++) acc += xs[j] * wr[j];
            float s = 1.0f / (1.0f + expf(-acc));
            semb[t] = s;
            out_emb[n * EMB + t] = s;
        }
        __syncthreads();

        if (t < 60) {
            float th = semb[2 * t]     * (0.5f * PIf);
            float ph = semb[2 * t + 1] * (2.0f * PIf);
            float st_, ct_, sp_, cp_;
            sincosf(th, &st_, &ct_);
            sincosf(ph, &sp_, &cp_);
            trig[t] = make_float4(ct_, st_, cp_, sp_);
        }
        __syncthreads();

        // 64 threads: t = c*8 + p ; thread holds rows 2p, 2p+1 of column c.
        if (t < 64) {
            const int p = t & 7;
            const int lane = t & 31;
            float2 t0 = make_float2((2 * p     == (t >> 3)) ? 1.0f : 0.0f, 0.0f);
            float2 t1 = make_float2((2 * p + 1 == (t >> 3)) ? 1.0f : 0.0f, 0.0f);

            const int NBF[8] = {0, 8, 15, 23, 30, 38, 45, 53};

            #pragma unroll
            for (int d = 0; d < 8; d++) {
                if ((d & 1) == 0) {
                    float4 tg = trig[NBF[d] + p];
                    float2 epct = make_float2(tg.z * tg.x, tg.w * tg.x);
                    float2 epst = make_float2(tg.z * tg.y, tg.w * tg.y);
                    float2 n0 = cmul(epct, t0);
                    n0.x -= tg.y * t1.x;  n0.y -= tg.y * t1.y;
                    float2 n1 = cmul(epst, t0);
                    n1.x += tg.x * t1.x;  n1.y += tg.x * t1.y;
                    t0 = n0;  t1 = n1;
                } else {
                    float2 vlow = t1;
                    float2 vhigh;
                    vhigh.x = __shfl_sync(0xFFFFFFFFu, t0.x, lane + 1, 32);
                    vhigh.y = __shfl_sync(0xFFFFFFFFu, t0.y, lane + 1, 32);
                    float2 nhigh = vhigh;
                    if (p < 7) {
                        float4 tg = trig[NBF[d] + p];
                        float2 epct = make_float2(tg.z * tg.x, tg.w * tg.x);
                        float2 epst = make_float2(tg.z * tg.y, tg.w * tg.y);
                        float2 nlow = cmul(epct, vlow);
                        nlow.x -= tg.y * vhigh.x;  nlow.y -= tg.y * vhigh.y;
                        nhigh = cmul(epst, vlow);
                        nhigh.x += tg.x * vhigh.x; nhigh.y += tg.x * vhigh.y;
                        t1 = nlow;
                    }
                    float2 back;
                    back.x = __shfl_sync(0xFFFFFFFFu, nhigh.x, lane - 1, 32);
                    back.y = __shfl_sync(0xFFFFFFFFu, nhigh.y, lane - 1, 32);
                    if (p > 0) t0 = back;
                }
            }

            const int c = t >> 3;
            g_V[n * (NPH * MODES) + c * MODES + 2 * p]     = t0;
            g_V[n * (NPH * MODES) + c * MODES + 2 * p + 1] = t1;
        }
        __syncthreads();
        if (tid == 0) {
            __threadfence();
            g_done[n] = 1u;   // publish
        }
    }

    // ---- pair phase (all blocks; one warp per pair) ----
    const int w    = tid >> 5;
    const int lane = tid & 31;
    const int Wp   = bid * 8 + w;   // pair index 0..32639

    // Decode strict upper triangle: largest b with b(b-1)/2 <= Wp, a = rem.
    int bq = (int)((1.0f + sqrtf(8.0f * (float)Wp + 1.0f)) * 0.5f);
    while (bq * (bq - 1) / 2 > Wp) bq--;
    while ((bq + 1) * bq / 2 <= Wp) bq++;
    const int bcol = bq;                       // 1..255
    const int a    = Wp - bq * (bq - 1) / 2;   // 0..bcol-1

    // Wait for both samples' V to be published
    if (lane == 0) {
        while (g_done[a]    == 0u) __nanosleep(64);
        while (g_done[bcol] == 0u) __nanosleep(64);
    }
    __syncwarp();
    __threadfence();   // acquire: order V loads after flag observation

    __shared__ alignas(16) float2 sVa[8][NPH * VROW];   // [w][i*18 + m]
    __shared__ alignas(16) float2 sVb[8][NPH * VROW];   // [w][j*18 + m]
    __shared__ alignas(16) ull    sAR[8][64];           // row-major: [w][i*8 + j]
    __shared__ alignas(16) ull    sRall[8][8];          // column sums over rows

    #pragma unroll
    for (int r = 0; r < 4; r++) {
        const int idx = lane + r * 32;
        const int row = idx >> 4, m = idx & 15;
        sVa[w][row * VROW + m] = g_V[a    * (NPH * MODES) + idx];
        sVb[w][row * VROW + m] = g_V[bcol * (NPH * MODES) + idx];
    }
    __syncwarp();

    // G[i][j] = sum_m conj(Va[m][i]) * Vb[m][j]; lane computes 2 entries.
    #pragma unroll
    for (int e = 0; e < 2; e++) {
        const int idx = lane + e * 32;
        const int i = idx >> 3, j = idx & 7;
        const float4* pa = (const float4*)&sVa[w][i * VROW];
        const float4* pb = (const float4*)&sVb[w][j * VROW];
        float2 acc = make_float2(0.0f, 0.0f);
        #pragma unroll
        for (int mm = 0; mm < 8; mm++) {
            float4 va2 = pa[mm];
            float4 vb2 = pb[mm];
            acc.x += va2.x * vb2.x + va2.y * vb2.y;
            acc.y += va2.x * vb2.y - va2.y * vb2.x;
            acc.x += va2.z * vb2.z + va2.w * vb2.w;
            acc.y += va2.z * vb2.w - va2.w * vb2.z;
        }
        sAR[w][idx] = pack2(acc.x, acc.y);   // row-major store: [i*8 + j]
    }
    __syncwarp();

    // Column sums over all rows: R_all[j] = sum_i G[i][j]  (lanes 0..7)
    if (lane < 8) {
        float2 s = make_float2(0.0f, 0.0f);
        #pragma unroll
        for (int i = 0; i < 8; i++) {
            float2 v = unpack2(sAR[w][i * 8 + lane]);
            s.x += v.x; s.y += v.y;
        }
        sRall[w][lane] = pack2(s.x, s.y);
    }
    __syncwarp();

    // Register-cache row 1 (delta bit 0: flips at k=1 and k=3).
    ull rr1[8];
    {
        const ulonglong2* r1 = (const ulonglong2*)&sAR[w][8];
        #pragma unroll
        for (int q = 0; q < 4; q++) {
            ulonglong2 v = r1[q];
            rr1[2*q] = v.x; rr1[2*q+1] = v.y;
        }
    }

    // Gray state: g = gray(4*lane) over 7 bits (bit b <-> row b+1); bit0 = 0.
    unsigned g = ((4u * lane) ^ (2u * lane)) & 0x7Fu;

    // Init S = R_all - 2 * sum_{set bits b=1..6} row_{b+1}
    ull S[8];
    {
        const ulonglong2* ra = (const ulonglong2*)&sRall[w][0];
        #pragma unroll
        for (int q = 0; q < 4; q++) {
            ulonglong2 v = ra[q];
            S[2*q] = v.x; S[2*q+1] = v.y;
        }
    }
    #pragma unroll
    for (int bb = 1; bb < 7; bb++) {
        const float msk = -2.0f * (float)((g >> bb) & 1u);
        const ull mp = pack2(msk, msk);
        const ulonglong2* row = (const ulonglong2*)&sAR[w][(bb + 1) * 8];
        #pragma unroll
        for (int q = 0; q < 4; q++) {
            ulonglong2 rv = row[q];
            S[2*q]   = ffma2p(mp, rv.x, S[2*q]);
            S[2*q+1] = ffma2p(mp, rv.y, S[2*q+1]);
        }
    }

    float2 acc = make_float2(0.0f, 0.0f);

    #pragma unroll
    for (int k = 0; k < 4; k++) {
        float2 s0 = unpack2(S[0]), s1 = unpack2(S[1]);
        float2 s2 = unpack2(S[2]), s3 = unpack2(S[3]);
        float2 s4 = unpack2(S[4]), s5 = unpack2(S[5]);
        float2 s6 = unpack2(S[6]), s7 = unpack2(S[7]);
        float2 p01 = cmul(s0, s1);
        float2 p23 = cmul(s2, s3);
        float2 p45 = cmul(s4, s5);
        float2 p67 = cmul(s6, s7);
        float2 p = cmul(cmul(p01, p23), cmul(p45, p67));
        if (k & 1) { acc.x -= p.x; acc.y -= p.y; }
        else       { acc.x += p.x; acc.y += p.y; }

        if (k < 3) {
            const int bb = (k == 1) ? 1 : 0;
            g ^= (1u << bb);
            const float s = ((g >> bb) & 1u) ? -2.0f : 2.0f;
            const ull sp = pack2(s, s);
            if (bb == 0) {
                #pragma unroll
                for (int i = 0; i < 8; i++) S[i] = ffma2p(sp, rr1[i], S[i]);
            } else {
                const ulonglong2* row = (const ulonglong2*)&sAR[w][2 * 8];
                #pragma unroll
                for (int q = 0; q < 4; q++) {
                    ulonglong2 rv = row[q];
                    S[2*q]   = ffma2p(sp, rv.x, S[2*q]);
                    S[2*q+1] = ffma2p(sp, rv.y, S[2*q+1]);
                }
            }
        }
    }

    // Warp reduce (complex)
    #pragma unroll
    for (int off = 16; off > 0; off >>= 1) {
        acc.x += __shfl_xor_sync(0xFFFFFFFFu, acc.x, off);
        acc.y += __shfl_xor_sync(0xFFFFFFFFu, acc.y, off);
    }

    if (lane == 0) {
        // perm = acc / 128 ; K = |perm|^2 = |acc|^2 / 16384
        float kv = (acc.x * acc.x + acc.y * acc.y) * (1.0f / 16384.0f);
        Kout[a * NSAMP + bcol] = kv;
        Kout[bcol * NSAMP + a] = kv;
    }

    // ---- completion: last block resets flags so every graph replay starts clean
    __syncthreads();
    if (tid == 0) {
        __threadfence();
        unsigned old = atomicAdd(&g_fin, 1u);
        if (old == (unsigned)(NBLK - 1)) {
            for (int i = 0; i < NSAMP; i++) g_done[i] = 0u;
            __threadfence();
            g_fin = 0u;
        }
    }
}

// ---------------------------------------------------------------------------
extern "C" void kernel_launch(void* const* d_in, const int* in_sizes, int n_in,
                              void* d_out, int out_size)
{
    const float* x = (const float*)d_in[0];   // (256, 64)
    const float* W = (const float*)d_in[1];   // (120, 64)
    const float* b = (const float*)d_in[2];   // (120,)
    float* out = (float*)d_out;               // [x_emb (30720) | K (65536)]

    fused_kernel<<<NBLK, 256>>>(x, W, b, out, out + NSAMP * EMB);
}

// round 17
// speedup vs baseline: 1.5113x; 1.5113x over previous
#include <cuda_runtime.h>
#include <cstdint>

#define NSAMP 256
#define EMB   120
#define DIN   64
#define MODES 16
#define NPH   8

#define PIf 3.14159265358979323846f

typedef unsigned long long ull;

// Persistent scratch for V, stored TRANSPOSED: [n][c][m] (c=0..7, m=0..15)
__device__ float2 g_V[NSAMP * NPH * MODES];

__device__ __forceinline__ float2 cmul(float2 a, float2 b) {
    return make_float2(a.x * b.x - a.y * b.y, a.x * b.y + a.y * b.x);
}

// Packed dual-FMA on native 64-bit operands (FFMA2, one issue slot)
__device__ __forceinline__ ull ffma2p(ull a, ull b, ull c) {
    ull d;
    asm("fma.rn.f32x2 %0, %1, %2, %3;" : "=l"(d) : "l"(a), "l"(b), "l"(c));
    return d;
}
union pk { ull u; float2 f; };
__device__ __forceinline__ ull pack2(float x, float y) {
    pk v; v.f = make_float2(x, y); return v.u;
}
__device__ __forceinline__ float2 unpack2(ull a) {
    pk v; v.u = a; return v.f;
}

// ---------------------------------------------------------------------------
// Kernel A: x_emb = sigmoid(x @ W^T + b); build V[n] (16x8 complex) per sample.
// Also writes the K diagonal (=1.0). Signals dependent launch via PDL.
// ---------------------------------------------------------------------------
__global__ void __launch_bounds__(128) emb_v_kernel(
    const float* __restrict__ x,
    const float* __restrict__ W,
    const float* __restrict__ b,
    float* __restrict__ out_emb,
    float* __restrict__ Kout)
{
    const int n = blockIdx.x;
    const int t = threadIdx.x;

    __shared__ float xs[DIN];
    __shared__ float semb[EMB];
    __shared__ float4 trig[60];

    if (t < DIN) xs[t] = x[n * DIN + t];
    if (t == 127) Kout[n * NSAMP + n] = 1.0f;   // diagonal of K
    __syncthreads();

    if (t < EMB) {
        float acc = b[t];
        const float* wr = W + t * DIN;
        #pragma unroll
        for (int j = 0; j < DIN; j++) acc += xs[j] * wr[j];
        float s = 1.0f / (1.0f + expf(-acc));
        semb[t] = s;
        out_emb[n * EMB + t] = s;
    }
    __syncthreads();

    if (t < 60) {
        float th = semb[2 * t]     * (0.5f * PIf);
        float ph = semb[2 * t + 1] * (2.0f * PIf);
        float st_, ct_, sp_, cp_;
        sincosf(th, &st_, &ct_);
        sincosf(ph, &sp_, &cp_);
        trig[t] = make_float4(ct_, st_, cp_, sp_);
    }
    __syncthreads();

    // 64 threads: tid = c*8 + p ; thread holds rows 2p, 2p+1 of column c.
    if (t < 64) {
        const int p = t & 7;
        const int lane = t & 31;
        float2 t0 = make_float2((2 * p     == (t >> 3)) ? 1.0f : 0.0f, 0.0f);
        float2 t1 = make_float2((2 * p + 1 == (t >> 3)) ? 1.0f : 0.0f, 0.0f);

        const int NBF[8] = {0, 8, 15, 23, 30, 38, 45, 53};

        #pragma unroll
        for (int d = 0; d < 8; d++) {
            if ((d & 1) == 0) {
                float4 tg = trig[NBF[d] + p];
                float2 epct = make_float2(tg.z * tg.x, tg.w * tg.x);
                float2 epst = make_float2(tg.z * tg.y, tg.w * tg.y);
                float2 n0 = cmul(epct, t0);
                n0.x -= tg.y * t1.x;  n0.y -= tg.y * t1.y;
                float2 n1 = cmul(epst, t0);
                n1.x += tg.x * t1.x;  n1.y += tg.x * t1.y;
                t0 = n0;  t1 = n1;
            } else {
                float2 vlow = t1;
                float2 vhigh;
                vhigh.x = __shfl_sync(0xFFFFFFFFu, t0.x, lane + 1, 32);
                vhigh.y = __shfl_sync(0xFFFFFFFFu, t0.y, lane + 1, 32);
                float2 nhigh = vhigh;
                if (p < 7) {
                    float4 tg = trig[NBF[d] + p];
                    float2 epct = make_float2(tg.z * tg.x, tg.w * tg.x);
                    float2 epst = make_float2(tg.z * tg.y, tg.w * tg.y);
                    float2 nlow = cmul(epct, vlow);
                    nlow.x -= tg.y * vhigh.x;  nlow.y -= tg.y * vhigh.y;
                    nhigh = cmul(epst, vlow);
                    nhigh.x += tg.x * vhigh.x; nhigh.y += tg.x * vhigh.y;
                    t1 = nlow;
                }
                float2 back;
                back.x = __shfl_sync(0xFFFFFFFFu, nhigh.x, lane - 1, 32);
                back.y = __shfl_sync(0xFFFFFFFFu, nhigh.y, lane - 1, 32);
                if (p > 0) t0 = back;
            }
        }

        const int c = t >> 3;
        g_V[n * (NPH * MODES) + c * MODES + 2 * p]     = t0;
        g_V[n * (NPH * MODES) + c * MODES + 2 * p + 1] = t1;
    }

    // All work for this block done -> allow dependent grid to launch.
    asm volatile("griddepcontrol.launch_dependents;");
}

// ---------------------------------------------------------------------------
// Kernel B (flat strict-upper-triangle, GLYNN): one warp per pair (a<b).
// ALU-only prelude (triangle decode) runs BEFORE griddepcontrol.wait so it
// overlaps with the producer kernel under PDL.
// ---------------------------------------------------------------------------
#define VROW 18   // padded row stride (float2 units)
#define NPAIR 32640

__global__ void __launch_bounds__(256, 4) pair_kernel_tri(float* __restrict__ Kout)
{
    const int tid  = threadIdx.x;
    const int w    = tid >> 5;
    const int lane = tid & 31;
    const int Wp   = blockIdx.x * 8 + w;   // pair index 0..32639

    // Decode strict upper triangle: largest b with b(b-1)/2 <= Wp, a = rem.
    int bq = (int)((1.0f + sqrtf(8.0f * (float)Wp + 1.0f)) * 0.5f);
    while (bq * (bq - 1) / 2 > Wp) bq--;
    while ((bq + 1) * bq / 2 <= Wp) bq++;
    const int bcol = bq;                       // 1..255
    const int a    = Wp - bq * (bq - 1) / 2;   // 0..bcol-1

    // PDL: wait until the producer grid's memory (g_V, K diag) is visible.
    asm volatile("griddepcontrol.wait;");

    __shared__ alignas(16) float2 sVa[8][NPH * VROW];   // [w][i*18 + m]
    __shared__ alignas(16) float2 sVb[8][NPH * VROW];   // [w][j*18 + m]
    __shared__ alignas(16) ull    sAR[8][64];           // row-major: [w][i*8 + j]
    __shared__ alignas(16) ull    sRall[8][8];          // column sums over rows

    #pragma unroll
    for (int r = 0; r < 4; r++) {
        const int idx = lane + r * 32;
        const int row = idx >> 4, m = idx & 15;
        sVa[w][row * VROW + m] = g_V[a    * (NPH * MODES) + idx];
        sVb[w][row * VROW + m] = g_V[bcol * (NPH * MODES) + idx];
    }
    __syncwarp();

    // G[i][j] = sum_m conj(Va[m][i]) * Vb[m][j]; lane computes 2 entries.
    #pragma unroll
    for (int e = 0; e < 2; e++) {
        const int idx = lane + e * 32;
        const int i = idx >> 3, j = idx & 7;
        const float4* pa = (const float4*)&sVa[w][i * VROW];
        const float4* pb = (const float4*)&sVb[w][j * VROW];
        float2 acc = make_float2(0.0f, 0.0f);
        #pragma unroll
        for (int mm = 0; mm < 8; mm++) {
            float4 va2 = pa[mm];
            float4 vb2 = pb[mm];
            acc.x += va2.x * vb2.x + va2.y * vb2.y;
            acc.y += va2.x * vb2.y - va2.y * vb2.x;
            acc.x += va2.z * vb2.z + va2.w * vb2.w;
            acc.y += va2.z * vb2.w - va2.w * vb2.z;
        }
        sAR[w][idx] = pack2(acc.x, acc.y);   // row-major store: [i*8 + j]
    }
    __syncwarp();

    // Column sums over all rows: R_all[j] = sum_i G[i][j]  (lanes 0..7)
    if (lane < 8) {
        float2 s = make_float2(0.0f, 0.0f);
        #pragma unroll
        for (int i = 0; i < 8; i++) {
            float2 v = unpack2(sAR[w][i * 8 + lane]);
            s.x += v.x; s.y += v.y;
        }
        sRall[w][lane] = pack2(s.x, s.y);
    }
    __syncwarp();

    // Register-cache row 1 (delta bit 0: flips at k=1 and k=3).
    ull rr1[8];
    {
        const ulonglong2* r1 = (const ulonglong2*)&sAR[w][8];
        #pragma unroll
        for (int q = 0; q < 4; q++) {
            ulonglong2 v = r1[q];
            rr1[2*q] = v.x; rr1[2*q+1] = v.y;
        }
    }

    // Gray state: g = gray(4*lane) over 7 bits (bit b <-> row b+1); bit0 = 0.
    unsigned g = ((4u * lane) ^ (2u * lane)) & 0x7Fu;

    // Init S = R_all - 2 * sum_{set bits b=1..6} row_{b+1}
    ull S[8];
    {
        const ulonglong2* ra = (const ulonglong2*)&sRall[w][0];
        #pragma unroll
        for (int q = 0; q < 4; q++) {
            ulonglong2 v = ra[q];
            S[2*q] = v.x; S[2*q+1] = v.y;
        }
    }
    #pragma unroll
    for (int bb = 1; bb < 7; bb++) {
        const float msk = -2.0f * (float)((g >> bb) & 1u);
        const ull mp = pack2(msk, msk);
        const ulonglong2* row = (const ulonglong2*)&sAR[w][(bb + 1) * 8];
        #pragma unroll
        for (int q = 0; q < 4; q++) {
            ulonglong2 rv = row[q];
            S[2*q]   = ffma2p(mp, rv.x, S[2*q]);
            S[2*q+1] = ffma2p(mp, rv.y, S[2*q+1]);
        }
    }

    float2 acc = make_float2(0.0f, 0.0f);

    #pragma unroll
    for (int k = 0; k < 4; k++) {
        float2 s0 = unpack2(S[0]), s1 = unpack2(S[1]);
        float2 s2 = unpack2(S[2]), s3 = unpack2(S[3]);
        float2 s4 = unpack2(S[4]), s5 = unpack2(S[5]);
        float2 s6 = unpack2(S[6]), s7 = unpack2(S[7]);
        float2 p01 = cmul(s0, s1);
        float2 p23 = cmul(s2, s3);
        float2 p45 = cmul(s4, s5);
        float2 p67 = cmul(s6, s7);
        float2 p = cmul(cmul(p01, p23), cmul(p45, p67));
        if (k & 1) { acc.x -= p.x; acc.y -= p.y; }
        else       { acc.x += p.x; acc.y += p.y; }

        if (k < 3) {
            const int bb = (k == 1) ? 1 : 0;
            g ^= (1u << bb);
            const float s = ((g >> bb) & 1u) ? -2.0f : 2.0f;
            const ull sp = pack2(s, s);
            if (bb == 0) {
                #pragma unroll
                for (int i = 0; i < 8; i++) S[i] = ffma2p(sp, rr1[i], S[i]);
            } else {
                const ulonglong2* row = (const ulonglong2*)&sAR[w][2 * 8];
                #pragma unroll
                for (int q = 0; q < 4; q++) {
                    ulonglong2 rv = row[q];
                    S[2*q]   = ffma2p(sp, rv.x, S[2*q]);
                    S[2*q+1] = ffma2p(sp, rv.y, S[2*q+1]);
                }
            }
        }
    }

    // Warp reduce (complex)
    #pragma unroll
    for (int off = 16; off > 0; off >>= 1) {
        acc.x += __shfl_xor_sync(0xFFFFFFFFu, acc.x, off);
        acc.y += __shfl_xor_sync(0xFFFFFFFFu, acc.y, off);
    }

    if (lane == 0) {
        // perm = acc / 128 ; K = |perm|^2 = |acc|^2 / 16384
        float kv = (acc.x * acc.x + acc.y * acc.y) * (1.0f / 16384.0f);
        Kout[a * NSAMP + bcol] = kv;
        Kout[bcol * NSAMP + a] = kv;
    }
}

// ---------------------------------------------------------------------------
extern "C" void kernel_launch(void* const* d_in, const int* in_sizes, int n_in,
                              void* d_out, int out_size)
{
    const float* x = (const float*)d_in[0];   // (256, 64)
    const float* W = (const float*)d_in[1];   // (120, 64)
    const float* b = (const float*)d_in[2];   // (120,)
    float* out = (float*)d_out;               // [x_emb (30720) | K (65536)]

    emb_v_kernel<<<NSAMP, 128>>>(x, W, b, out, out + NSAMP * EMB);

    // Dependent launch with programmatic stream serialization (PDL):
    // pair kernel may begin its prelude while emb kernel is still running;
    // griddepcontrol.wait inside provides the ordering + visibility.
    cudaLaunchConfig_t cfg = {};
    cfg.gridDim  = dim3(NPAIR / 8);
    cfg.blockDim = dim3(256);
    cudaLaunchAttribute attrs[1];
    attrs[0].id = cudaLaunchAttributeProgrammaticStreamSerialization;
    attrs[0].val.programmaticStreamSerializationAllowed = 1;
    cfg.attrs = attrs;
    cfg.numAttrs = 1;
    float* kptr = out + NSAMP * EMB;
    cudaError_t e = cudaLaunchKernelEx(&cfg, pair_kernel_tri, kptr);
    if (e != cudaSuccess) {
        // Fallback: plain dependent launch (identical semantics, no overlap)
        pair_kernel_tri<<<NPAIR / 8, 256>>>(kptr);
    }
}